// round 1
// baseline (speedup 1.0000x reference)
#include <cuda_runtime.h>
#include <math.h>

#define NN 50000
#define EE 800000
#define DD 200
#define RR 230

// ---- scratch (no allocations allowed; __device__ globals) ----
__device__ __align__(128) float g_agg[NN * DD];   // edge aggregation / h2 (in-place)
__device__ __align__(128) float g_h1[NN * DD];    // layer-1 output
__device__ __align__(128) float g_norm[NN];       // deg -> 1/deg
__device__ __align__(128) float g_WtA[DD * DD];   // W_ih^T (k-major)
__device__ __align__(128) float g_WtB[DD * DD];   // W_hh^T (k-major)

// ---------------- degree / norm ----------------
__global__ void deg_kernel(const int* __restrict__ dst) {
    int e = blockIdx.x * blockDim.x + threadIdx.x;
    if (e < EE) atomicAdd(&g_norm[dst[e]], 1.0f);
}

__global__ void norm_kernel() {
    int n = blockIdx.x * blockDim.x + threadIdx.x;
    if (n < NN) {
        float d = g_norm[n];
        g_norm[n] = (d > 0.0f) ? (1.0f / d) : 0.0f;
    }
}

// ---------------- transpose W_ih, W_hh to k-major ----------------
__global__ void transpose_kernel(const float* __restrict__ A, const float* __restrict__ B) {
    int idx = blockIdx.x * blockDim.x + threadIdx.x;
    if (idx < DD * DD) {
        int j = idx / DD, k = idx - j * DD;
        g_WtA[k * DD + j] = A[idx];
        g_WtB[k * DD + j] = B[idx];
    }
}

// ---------------- edge message + scatter ----------------
// One thread handles one edge and TWO S=2 diagonal blocks -> 4 consecutive
// outputs -> a single red.global.add.v4.f32 (4x fewer atomic ops than scalar).
// w layout: (R, B, S, S) flat = r*400 + b*4 + i*2 + o.
__global__ void edge_kernel(const float* __restrict__ x,
                            const int* __restrict__ src,
                            const int* __restrict__ dst,
                            const int* __restrict__ et,
                            const float* __restrict__ w) {
    long idx = (long)blockIdx.x * blockDim.x + threadIdx.x;
    if (idx >= (long)EE * 50) return;
    int e  = (int)(idx / 50);
    int b2 = (int)(idx - (long)e * 50);   // pair of blocks: b = 2*b2, 2*b2+1

    int s = __ldg(&src[e]);
    int d = __ldg(&dst[e]);
    int r = __ldg(&et[e]);

    float4 xv = *(const float4*)(x + (long)s * DD + b2 * 4);       // x0,x1 | x0',x1'
    const float4* wp = (const float4*)(w + (long)r * 400 + b2 * 8);
    float4 wA = wp[0];   // block b:   {i0o0, i0o1, i1o0, i1o1}
    float4 wB = wp[1];   // block b+1

    float o0 = xv.x * wA.x + xv.y * wA.z;
    float o1 = xv.x * wA.y + xv.y * wA.w;
    float o2 = xv.z * wB.x + xv.w * wB.z;
    float o3 = xv.z * wB.y + xv.w * wB.w;

    float* ap = g_agg + (long)d * DD + b2 * 4;   // 16B aligned
    asm volatile("red.global.add.v4.f32 [%0], {%1, %2, %3, %4};"
                 :: "l"(ap), "f"(o0), "f"(o1), "f"(o2), "f"(o3) : "memory");
}

// ---------------- fused GEMM + combine ----------------
// out[row, col] = act( sum_k A[row,k]*W[k,col]  (+ sum_k A2[row,k]*W2[k,col])
//                      (+ agg[row,col]*norm[row]) + bias[col] (+ bias2[col]) )
// W2 taken from device symbols when DUAL (final stage uses g_WtA/g_WtB).
// Tile: BM=64 rows x BN=128 cols, blockDim(32,8), per-thread 8x4 register tile.
template <bool DUAL, bool TANH, bool HAS_AGG, bool W_FROM_SYM>
__global__ __launch_bounds__(256) void gemm_kernel(
    const float* __restrict__ A,  const float* __restrict__ Win,
    const float* __restrict__ A2,
    const float* __restrict__ bias, const float* __restrict__ bias2,
    float* __restrict__ out) {
    __shared__ float Wsh[50 * 128];
    __shared__ float Xsh[64 * 50];

    int tx = threadIdx.x, ty = threadIdx.y;
    int tid = ty * 32 + tx;
    int rowbase = blockIdx.y * 64;
    int colbase = blockIdx.x * 128;

    float acc[8][4];
#pragma unroll
    for (int m = 0; m < 8; m++)
#pragma unroll
        for (int c = 0; c < 4; c++) acc[m][c] = 0.0f;

#pragma unroll
    for (int p = 0; p < (DUAL ? 2 : 1); p++) {
        const float* Ap = p ? A2 : A;
        const float* Wp = W_FROM_SYM ? (p ? g_WtB : g_WtA) : Win;
        for (int kb = 0; kb < DD; kb += 50) {
            __syncthreads();
            // load W tile [50 x 128]
            for (int i = tid; i < 50 * 128; i += 256) {
                int k = i >> 7, c = i & 127;
                int gc = colbase + c;
                Wsh[i] = (gc < DD) ? Wp[(kb + k) * DD + gc] : 0.0f;
            }
            // load X tile [64 x 50]
            for (int i = tid; i < 64 * 50; i += 256) {
                int m = i / 50, k = i - m * 50;
                int gr = rowbase + m;
                Xsh[i] = (gr < NN) ? Ap[(long)gr * DD + kb + k] : 0.0f;
            }
            __syncthreads();
#pragma unroll 2
            for (int k = 0; k < 50; k++) {
                float4 wv = *(const float4*)(Wsh + k * 128 + tx * 4);
#pragma unroll
                for (int m = 0; m < 8; m++) {
                    float xm = Xsh[(ty * 8 + m) * 50 + k];
                    acc[m][0] += xm * wv.x;
                    acc[m][1] += xm * wv.y;
                    acc[m][2] += xm * wv.z;
                    acc[m][3] += xm * wv.w;
                }
            }
        }
    }

    int col = colbase + tx * 4;
    if (col >= DD) return;   // whole float4 out of range (DD % 4 == 0)
    float4 bb = *(const float4*)(bias + col);
    float4 b2v = make_float4(0.f, 0.f, 0.f, 0.f);
    if (DUAL) b2v = *(const float4*)(bias2 + col);
#pragma unroll
    for (int m = 0; m < 8; m++) {
        int row = rowbase + ty * 8 + m;
        if (row >= NN) break;
        float4 v = make_float4(acc[m][0], acc[m][1], acc[m][2], acc[m][3]);
        if (HAS_AGG) {
            float nv = g_norm[row];
            float4 a = *(const float4*)(g_agg + (long)row * DD + col);
            v.x += a.x * nv; v.y += a.y * nv; v.z += a.z * nv; v.w += a.w * nv;
        }
        v.x += bb.x; v.y += bb.y; v.z += bb.z; v.w += bb.w;
        if (DUAL) { v.x += b2v.x; v.y += b2v.y; v.z += b2v.z; v.w += b2v.w; }
        if (TANH) { v.x = tanhf(v.x); v.y = tanhf(v.y); v.z = tanhf(v.z); v.w = tanhf(v.w); }
        *(float4*)(out + (long)row * DD + col) = v;
    }
}

// ---------------- launch ----------------
extern "C" void kernel_launch(void* const* d_in, const int* in_sizes, int n_in,
                              void* d_out, int out_size) {
    const float* node_feat = (const float*)d_in[0];
    const float* dyn       = (const float*)d_in[1];   // (N,1,D) contiguous
    const int*   src       = (const int*)d_in[2];
    const int*   dst       = (const int*)d_in[3];
    const int*   et        = (const int*)d_in[4];
    const float* w1        = (const float*)d_in[5];
    const float* lw1       = (const float*)d_in[6];
    const float* b1        = (const float*)d_in[7];
    const float* w2        = (const float*)d_in[8];
    const float* lw2       = (const float*)d_in[9];
    const float* b2        = (const float*)d_in[10];
    const float* Wih       = (const float*)d_in[11];
    const float* Whh       = (const float*)d_in[12];
    const float* bih       = (const float*)d_in[13];
    const float* bhh       = (const float*)d_in[14];
    float* out = (float*)d_out;

    void *agg_p, *norm_p, *h1_p;
    cudaGetSymbolAddress(&agg_p, g_agg);
    cudaGetSymbolAddress(&norm_p, g_norm);
    cudaGetSymbolAddress(&h1_p, g_h1);

    cudaMemsetAsync(agg_p, 0, sizeof(float) * NN * DD);
    cudaMemsetAsync(norm_p, 0, sizeof(float) * NN);

    deg_kernel<<<(EE + 255) / 256, 256>>>(dst);
    norm_kernel<<<(NN + 255) / 256, 256>>>();
    transpose_kernel<<<(DD * DD + 255) / 256, 256>>>(Wih, Whh);

    const long edge_threads = (long)EE * 50;
    const int edge_blocks = (int)((edge_threads + 255) / 256);

    dim3 blk(32, 8), grd(2, (NN + 63) / 64);

    // layer 1: scatter messages, then h1 = tanh(agg*norm + x@lw1 + b1)
    edge_kernel<<<edge_blocks, 256>>>(node_feat, src, dst, et, w1);
    gemm_kernel<false, true, true, false><<<grd, blk>>>(
        node_feat, lw1, nullptr, b1, nullptr, (float*)h1_p);

    // layer 2: h2 = agg2*norm + h1@lw2 + b2   (written in-place into g_agg)
    cudaMemsetAsync(agg_p, 0, sizeof(float) * NN * DD);
    edge_kernel<<<edge_blocks, 256>>>((const float*)h1_p, src, dst, et, w2);
    gemm_kernel<false, false, true, false><<<grd, blk>>>(
        (const float*)h1_p, lw2, nullptr, b2, nullptr, (float*)agg_p);

    // final: out = tanh(h2 @ Wih^T + h0 @ Whh^T + bih + bhh)
    gemm_kernel<true, true, false, true><<<grd, blk>>>(
        (const float*)agg_p, nullptr, dyn, bih, bhh, out);
}